// round 10
// baseline (speedup 1.0000x reference)
#include <cuda_runtime.h>
#include <cuda_fp16.h>
#include <cstdint>
#include <cstddef>
#include <math.h>

// ---------------------------------------------------------------------------
// Problem dims (fixed by the dataset)
// ---------------------------------------------------------------------------
#define MDIM 16384          // B*S = 8*2048
#define NDIM 4096           // D_OUT
#define KDIM 4096           // D_IN

#define BM 128
#define BN 256
#define BK 64               // fp16 elements per k-stage (128 bytes per row)
#define STAGES 4
#define NITER (KDIM / BK)   // 64

// Stage layout: [A 16KB][B 32KB] per stage, 4 stages = 192KB dynamic smem
#define STAGE_A   16384
#define STAGE_B   32768
#define STAGE_BYTES (STAGE_A + STAGE_B)
#define SMEM_BYTES (STAGES * STAGE_BYTES)

// ---------------------------------------------------------------------------
// Device scratch (static globals: no allocation in kernel_launch)
// ---------------------------------------------------------------------------
__device__ __half g_A[(size_t)MDIM * KDIM];   // 128 MB: x as fp16
__device__ __half g_B[(size_t)NDIM * KDIM];   // 32 MB: ternary weights {-1,0,1}
__device__ double g_partial[4096];
__device__ float  g_gamma;

// ---------------------------------------------------------------------------
// PTX helpers (family-portable: cp.async / ldmatrix / mma.sync only)
// ---------------------------------------------------------------------------
__device__ __forceinline__ uint32_t s2u(const void* p) {
    return (uint32_t)__cvta_generic_to_shared(p);
}

__device__ __forceinline__ void cp_async16(uint32_t smem_dst, const void* gmem_src) {
    asm volatile("cp.async.cg.shared.global [%0], [%1], 16;"
                 :: "r"(smem_dst), "l"(gmem_src));
}
__device__ __forceinline__ void cp_commit() {
    asm volatile("cp.async.commit_group;");
}
__device__ __forceinline__ void cp_waitp() {
    asm volatile("cp.async.wait_group %0;" :: "n"(STAGES - 2));
}

__device__ __forceinline__ void ldmatrix_x4(uint32_t& r0, uint32_t& r1, uint32_t& r2,
                                            uint32_t& r3, uint32_t addr) {
    asm volatile("ldmatrix.sync.aligned.m8n8.x4.shared.b16 {%0,%1,%2,%3}, [%4];"
                 : "=r"(r0), "=r"(r1), "=r"(r2), "=r"(r3) : "r"(addr));
}

__device__ __forceinline__ void mma_f16(float& c0, float& c1, float& c2, float& c3,
                                        uint32_t a0, uint32_t a1, uint32_t a2, uint32_t a3,
                                        uint32_t b0, uint32_t b1) {
    asm volatile("mma.sync.aligned.m16n8k16.row.col.f32.f16.f16.f32 "
                 "{%0,%1,%2,%3}, {%4,%5,%6,%7}, {%8,%9}, {%0,%1,%2,%3};"
                 : "+f"(c0), "+f"(c1), "+f"(c2), "+f"(c3)
                 : "r"(a0), "r"(a1), "r"(a2), "r"(a3), "r"(b0), "r"(b1));
}

// ---------------------------------------------------------------------------
// Prep kernels
// ---------------------------------------------------------------------------
// gamma = mean|w|, deterministic two-stage double tree.
__global__ void k_reduce1(const float* __restrict__ w) {
    __shared__ double sdata[256];
    const float* p = w + (size_t)blockIdx.x * 4096;
    double s = 0.0;
    for (int i = threadIdx.x; i < 4096; i += 256) s += (double)fabsf(p[i]);
    sdata[threadIdx.x] = s;
    __syncthreads();
    for (int st = 128; st > 0; st >>= 1) {
        if (threadIdx.x < st) sdata[threadIdx.x] += sdata[threadIdx.x + st];
        __syncthreads();
    }
    if (threadIdx.x == 0) g_partial[blockIdx.x] = sdata[0];
}
__global__ void k_reduce2() {
    __shared__ double sdata[256];
    double s = 0.0;
    for (int i = threadIdx.x; i < 4096; i += 256) s += g_partial[i];
    sdata[threadIdx.x] = s;
    __syncthreads();
    for (int st = 128; st > 0; st >>= 1) {
        if (threadIdx.x < st) sdata[threadIdx.x] += sdata[threadIdx.x + st];
        __syncthreads();
    }
    if (threadIdx.x == 0) g_gamma = (float)(sdata[0] / 16777216.0);
}

// Quantize weights to ternary fp16 {-1,0,1} (the *h scale applied in epilogue).
// Exact reference op order: clip(round(w / (gamma+eps) * half), -half, half) = half*t.
__global__ void k_quantw(const float* __restrict__ w, float halfv) {
    size_t i4 = (size_t)blockIdx.x * blockDim.x + threadIdx.x;   // float4 index, exact grid
    float gamma = g_gamma;
    float denom = gamma + 1e-8f;
    float4 v = reinterpret_cast<const float4*>(w)[i4];
    __half o[4];
    float q;
    q = rintf(v.x / denom * halfv); o[0] = __float2half(fminf(fmaxf(q, -1.0f), 1.0f));
    q = rintf(v.y / denom * halfv); o[1] = __float2half(fminf(fmaxf(q, -1.0f), 1.0f));
    q = rintf(v.z / denom * halfv); o[2] = __float2half(fminf(fmaxf(q, -1.0f), 1.0f));
    q = rintf(v.w / denom * halfv); o[3] = __float2half(fminf(fmaxf(q, -1.0f), 1.0f));
    reinterpret_cast<uint64_t*>(g_B)[i4] = *reinterpret_cast<uint64_t*>(o);
}

// Convert x (fp32) -> fp16 plane.
__global__ void k_convx(const float* __restrict__ x) {
    size_t i4 = (size_t)blockIdx.x * blockDim.x + threadIdx.x;   // float4 index, exact grid
    float4 v = reinterpret_cast<const float4*>(x)[i4];
    __half o[4];
    o[0] = __float2half(v.x);
    o[1] = __float2half(v.y);
    o[2] = __float2half(v.z);
    o[3] = __float2half(v.w);
    reinterpret_cast<uint64_t*>(g_A)[i4] = *reinterpret_cast<uint64_t*>(o);
}

// ---------------------------------------------------------------------------
// Main GEMM: mma.sync fp16, BM=128 x BN=256 x BK=64, 4-stage cp.async, 1 CTA/SM
// 8 warps: 2 (m) x 4 (n); warp tile 64x64; out = acc*half + bias
// ---------------------------------------------------------------------------
__global__ void __launch_bounds__(256, 1) k_gemm(
    const float* __restrict__ bias,
    float* __restrict__ out,
    float halfv)
{
    extern __shared__ char smem[];
    const uint32_t sb = s2u(smem);
    const int tid = threadIdx.x;
    const int wid = tid >> 5;
    const int lane = tid & 31;
    const int wm = wid >> 2;         // 0..1  (64-row m slab)
    const int wn = wid & 3;          // 0..3  (64-col n slab)

    const int nt_blk = blockIdx.x & 15;      // nt fastest: B tile reuse in L2
    const int mt_blk = blockIdx.x >> 4;
    const int m0 = mt_blk * BM;
    const int n0 = nt_blk * BN;

    const __half* gA = g_A;
    const __half* gB = g_B;

    // --- cp.async mapping ---
    // A: 2 threads/row (128 rows), 4 chunks each
    const int a_row = tid >> 1;
    const int a_cb  = (tid & 1) * 4;
    const size_t a_goff = (size_t)(m0 + a_row) * KDIM;
    const uint32_t a_srow = sb + a_row * 128;
    const int a_sw = a_row & 7;
    // B: 1 thread/row (256 rows), 8 chunks each
    const size_t b_goff = (size_t)(n0 + tid) * KDIM;
    const uint32_t b_srow = sb + STAGE_A + tid * 128;
    const int b_sw = tid & 7;

    float acc[4][8][4];
    #pragma unroll
    for (int i = 0; i < 4; i++)
        #pragma unroll
        for (int j = 0; j < 8; j++)
            #pragma unroll
            for (int k = 0; k < 4; k++) acc[i][j][k] = 0.0f;

    // --- prologue: issue stages 0..STAGES-2 ---
    #pragma unroll
    for (int s = 0; s < STAGES - 1; s++) {
        const int kk = s * BK;
        #pragma unroll
        for (int j = 0; j < 4; j++) {
            int c = a_cb + j;
            cp_async16(a_srow + s * STAGE_BYTES + ((c ^ a_sw) << 4),
                       gA + a_goff + kk + c * 8);
        }
        #pragma unroll
        for (int c = 0; c < 8; c++) {
            cp_async16(b_srow + s * STAGE_BYTES + ((c ^ b_sw) << 4),
                       gB + b_goff + kk + c * 8);
        }
        cp_commit();
    }

    int smem_read = 0, smem_write = STAGES - 1;

    for (int it = 0; it < NITER; ++it) {
        cp_waitp();
        __syncthreads();

        // issue loads for it + STAGES - 1
        const int itn = it + STAGES - 1;
        if (itn < NITER) {
            const int kk = itn * BK;
            #pragma unroll
            for (int j = 0; j < 4; j++) {
                int c = a_cb + j;
                cp_async16(a_srow + smem_write * STAGE_BYTES + ((c ^ a_sw) << 4),
                           gA + a_goff + kk + c * 8);
            }
            #pragma unroll
            for (int c = 0; c < 8; c++) {
                cp_async16(b_srow + smem_write * STAGE_BYTES + ((c ^ b_sw) << 4),
                           gB + b_goff + kk + c * 8);
            }
        }
        cp_commit();

        // --- compute current stage: 4 k-steps of k16 ---
        const uint32_t aBase = sb + smem_read * STAGE_BYTES;
        const uint32_t bBase = aBase + STAGE_A;
        const int lr = lane & 15;
        const int lc = lane >> 4;

        #pragma unroll
        for (int ks = 0; ks < 4; ks++) {
            uint32_t a[4][4];
            uint32_t b[8][2];
            const int c = ks * 2 + lc;
            #pragma unroll
            for (int mt = 0; mt < 4; mt++) {
                int r = wm * 64 + mt * 16 + lr;
                uint32_t ad = aBase + r * 128 + (((c ^ (r & 7))) << 4);
                ldmatrix_x4(a[mt][0], a[mt][1], a[mt][2], a[mt][3], ad);
            }
            #pragma unroll
            for (int nh = 0; nh < 4; nh++) {
                int r = wn * 64 + nh * 16 + lr;
                uint32_t bd = bBase + r * 128 + (((c ^ (r & 7))) << 4);
                uint32_t t0, t1, t2, t3;
                ldmatrix_x4(t0, t1, t2, t3, bd);
                b[nh * 2 + 0][0] = t0; b[nh * 2 + 0][1] = t2;
                b[nh * 2 + 1][0] = t1; b[nh * 2 + 1][1] = t3;
            }
            #pragma unroll
            for (int mt = 0; mt < 4; mt++)
                #pragma unroll
                for (int nt = 0; nt < 8; nt++)
                    mma_f16(acc[mt][nt][0], acc[mt][nt][1], acc[mt][nt][2], acc[mt][nt][3],
                            a[mt][0], a[mt][1], a[mt][2], a[mt][3],
                            b[nt][0], b[nt][1]);
        }

        smem_read = (smem_read + 1 == STAGES) ? 0 : smem_read + 1;
        smem_write = (smem_write + 1 == STAGES) ? 0 : smem_write + 1;
    }

    // --- epilogue: out = acc*half + bias ---
    const int mbase = m0 + wm * 64;
    const int nbase = n0 + wn * 64;
    const int lrow = lane >> 2;
    const int lcol = (lane & 3) * 2;

    #pragma unroll
    for (int nt = 0; nt < 8; nt++) {
        const int col = nbase + nt * 8 + lcol;
        const float bx = __ldg(&bias[col]);
        const float by = __ldg(&bias[col + 1]);
        #pragma unroll
        for (int mt = 0; mt < 4; mt++) {
            const int row0 = mbase + mt * 16 + lrow;
            float2 v0, v1;
            v0.x = acc[mt][nt][0] * halfv + bx;
            v0.y = acc[mt][nt][1] * halfv + by;
            v1.x = acc[mt][nt][2] * halfv + bx;
            v1.y = acc[mt][nt][3] * halfv + by;
            *reinterpret_cast<float2*>(out + (size_t)row0 * NDIM + col) = v0;
            *reinterpret_cast<float2*>(out + (size_t)(row0 + 8) * NDIM + col) = v1;
        }
    }
}

// ---------------------------------------------------------------------------
// Host launch
// ---------------------------------------------------------------------------
extern "C" void kernel_launch(void* const* d_in, const int* in_sizes, int n_in,
                              void* d_out, int out_size) {
    // Identify inputs by size: x=67108864, w=16777216, bias=4096
    const float* x = nullptr; const float* w = nullptr; const float* bias = nullptr;
    for (int i = 0; i < n_in; i++) {
        if (in_sizes[i] == MDIM * KDIM)      x = (const float*)d_in[i];
        else if (in_sizes[i] == NDIM * KDIM) w = (const float*)d_in[i];
        else if (in_sizes[i] == NDIM)        bias = (const float*)d_in[i];
    }
    float* out = (float*)d_out;

    const float halfv = (float)((pow(2.0, 1.58) - 1.0) * 0.5);

    // Prep: gamma (deterministic), W -> ternary fp16, X -> fp16
    k_reduce1<<<4096, 256>>>(w);
    k_reduce2<<<1, 256>>>();
    k_quantw<<<(NDIM * KDIM) / (256 * 4), 256>>>(w, halfv);
    k_convx<<<(MDIM * KDIM) / (256 * 4), 256>>>(x);

    // GEMM
    static bool attr_set = false;
    if (!attr_set) {
        cudaFuncSetAttribute(k_gemm, cudaFuncAttributeMaxDynamicSharedMemorySize, SMEM_BYTES);
        attr_set = true;
    }
    dim3 grid((MDIM / BM) * (NDIM / BN));   // 128 * 16 = 2048 CTAs
    k_gemm<<<grid, 256, SMEM_BYTES>>>(bias, out, halfv);
}

// round 11
// speedup vs baseline: 1.0892x; 1.0892x over previous
#include <cuda_runtime.h>
#include <cuda_fp16.h>
#include <cstdint>
#include <cstddef>
#include <math.h>

// ---------------------------------------------------------------------------
// Problem dims (fixed by the dataset)
// ---------------------------------------------------------------------------
#define MDIM 16384          // B*S = 8*2048
#define NDIM 4096           // D_OUT
#define KDIM 4096           // D_IN

#define BM 128
#define BN 128
#define BK 64               // fp16 elements per stage (128 bytes per row)
#define STAGES 3
#define NITER (KDIM / BK)   // 64

// Stage layout: [A 16KB][B 16KB] per stage, 3 stages = 96KB dynamic smem
#define STAGE_BYTES 32768
#define SMEM_BYTES (STAGES * STAGE_BYTES)

// ---------------------------------------------------------------------------
// Device scratch (static globals: no allocation in kernel_launch)
// ---------------------------------------------------------------------------
__device__ __half g_A[(size_t)MDIM * KDIM];   // 128 MB: x as fp16 (single plane)
__device__ __half g_B[(size_t)NDIM * KDIM];   // 32 MB: ternary weights {-1,0,1}
__device__ double g_partial[4096];
__device__ float  g_gamma;

// ---------------------------------------------------------------------------
// PTX helpers (family-portable: cp.async / ldmatrix / mma.sync only)
// ---------------------------------------------------------------------------
__device__ __forceinline__ uint32_t s2u(const void* p) {
    return (uint32_t)__cvta_generic_to_shared(p);
}

__device__ __forceinline__ void cp_async16(uint32_t smem_dst, const void* gmem_src) {
    asm volatile("cp.async.cg.shared.global [%0], [%1], 16;"
                 :: "r"(smem_dst), "l"(gmem_src));
}
__device__ __forceinline__ void cp_commit() {
    asm volatile("cp.async.commit_group;");
}
__device__ __forceinline__ void cp_wait1() {
    asm volatile("cp.async.wait_group 1;");
}

__device__ __forceinline__ void ldmatrix_x4(uint32_t& r0, uint32_t& r1, uint32_t& r2,
                                            uint32_t& r3, uint32_t addr) {
    asm volatile("ldmatrix.sync.aligned.m8n8.x4.shared.b16 {%0,%1,%2,%3}, [%4];"
                 : "=r"(r0), "=r"(r1), "=r"(r2), "=r"(r3) : "r"(addr));
}

// f16-accumulate HMMA: D(f16x2 x2) = A*B + C(f16x2 x2)
__device__ __forceinline__ void mma_f16acc(uint32_t& c0, uint32_t& c1,
                                           uint32_t a0, uint32_t a1, uint32_t a2, uint32_t a3,
                                           uint32_t b0, uint32_t b1) {
    asm volatile("mma.sync.aligned.m16n8k16.row.col.f16.f16.f16.f16 "
                 "{%0,%1}, {%2,%3,%4,%5}, {%6,%7}, {%0,%1};"
                 : "+r"(c0), "+r"(c1)
                 : "r"(a0), "r"(a1), "r"(a2), "r"(a3), "r"(b0), "r"(b1));
}

// ---------------------------------------------------------------------------
// Prep kernels
// ---------------------------------------------------------------------------
// gamma = mean|w|, deterministic two-stage double tree.
__global__ void k_reduce1(const float* __restrict__ w) {
    __shared__ double sdata[256];
    const float* p = w + (size_t)blockIdx.x * 4096;
    double s = 0.0;
    for (int i = threadIdx.x; i < 4096; i += 256) s += (double)fabsf(p[i]);
    sdata[threadIdx.x] = s;
    __syncthreads();
    for (int st = 128; st > 0; st >>= 1) {
        if (threadIdx.x < st) sdata[threadIdx.x] += sdata[threadIdx.x + st];
        __syncthreads();
    }
    if (threadIdx.x == 0) g_partial[blockIdx.x] = sdata[0];
}
__global__ void k_reduce2() {
    __shared__ double sdata[256];
    double s = 0.0;
    for (int i = threadIdx.x; i < 4096; i += 256) s += g_partial[i];
    sdata[threadIdx.x] = s;
    __syncthreads();
    for (int st = 128; st > 0; st >>= 1) {
        if (threadIdx.x < st) sdata[threadIdx.x] += sdata[threadIdx.x + st];
        __syncthreads();
    }
    if (threadIdx.x == 0) g_gamma = (float)(sdata[0] / 16777216.0);
}

// Quantize weights to ternary fp16 {-1,0,1} (the *h scale applied in epilogue).
// Exact reference op order: clip(round(w / (gamma+eps) * half), -half, half) = half*t.
__global__ void k_quantw(const float* __restrict__ w, float halfv) {
    size_t i4 = (size_t)blockIdx.x * blockDim.x + threadIdx.x;   // float4 index, exact grid
    float gamma = g_gamma;
    float denom = gamma + 1e-8f;
    float4 v = reinterpret_cast<const float4*>(w)[i4];
    __half o[4];
    float q;
    q = rintf(v.x / denom * halfv); o[0] = __float2half(fminf(fmaxf(q, -1.0f), 1.0f));
    q = rintf(v.y / denom * halfv); o[1] = __float2half(fminf(fmaxf(q, -1.0f), 1.0f));
    q = rintf(v.z / denom * halfv); o[2] = __float2half(fminf(fmaxf(q, -1.0f), 1.0f));
    q = rintf(v.w / denom * halfv); o[3] = __float2half(fminf(fmaxf(q, -1.0f), 1.0f));
    reinterpret_cast<uint64_t*>(g_B)[i4] = *reinterpret_cast<uint64_t*>(o);
}

// Convert x (fp32) -> fp16 plane.
__global__ void k_convx(const float* __restrict__ x) {
    size_t i4 = (size_t)blockIdx.x * blockDim.x + threadIdx.x;   // float4 index, exact grid
    float4 v = reinterpret_cast<const float4*>(x)[i4];
    __half o[4];
    o[0] = __float2half(v.x);
    o[1] = __float2half(v.y);
    o[2] = __float2half(v.z);
    o[3] = __float2half(v.w);
    reinterpret_cast<uint64_t*>(g_A)[i4] = *reinterpret_cast<uint64_t*>(o);
}

// ---------------------------------------------------------------------------
// Main GEMM: mma.sync fp16 with f16 accumulators chained over K=64, folded
// to f32 每 iteration. BM=128 x BN=128 x BK=64, 3-stage cp.async, 2 CTA/SM.
// 8 warps: 2 (m) x 4 (n); warp tile 64x32; out = acc*half + bias
// ---------------------------------------------------------------------------
__global__ void __launch_bounds__(256, 2) k_gemm(
    const float* __restrict__ bias,
    float* __restrict__ out,
    float halfv)
{
    extern __shared__ char smem[];
    const uint32_t sb = s2u(smem);
    const int tid = threadIdx.x;
    const int wid = tid >> 5;
    const int lane = tid & 31;
    const int wm = wid >> 2;         // 0..1
    const int wn = wid & 3;          // 0..3

    const int nt_blk = blockIdx.x & 31;      // nt fastest: B tile reuse in L2
    const int mt_blk = blockIdx.x >> 5;
    const int m0 = mt_blk * BM;
    const int n0 = nt_blk * BN;

    const __half* gA = g_A;
    const __half* gB = g_B;

    // --- per-thread cp.async mapping: 2 threads per row, 4x16B chunks each ---
    const int ldrow = tid >> 1;               // 0..127
    const int ldcb  = (tid & 1) * 4;          // chunk base 0 or 4
    const size_t a_row_off = (size_t)(m0 + ldrow) * KDIM;
    const size_t b_row_off = (size_t)(n0 + ldrow) * KDIM;
    const uint32_t a_smem_row = sb + ldrow * 128;
    const uint32_t b_smem_row = sb + 16384 + ldrow * 128;
    const int rsw = ldrow & 7;

    float acc[4][4][4];
    #pragma unroll
    for (int i = 0; i < 4; i++)
        #pragma unroll
        for (int j = 0; j < 4; j++)
            #pragma unroll
            for (int k = 0; k < 4; k++) acc[i][j][k] = 0.0f;

    // --- prologue: issue stages 0..STAGES-2 ---
    #pragma unroll
    for (int s = 0; s < STAGES - 1; s++) {
        const int kk = s * BK;
        #pragma unroll
        for (int j = 0; j < 4; j++) {
            int c = ldcb + j;
            cp_async16(a_smem_row + s * STAGE_BYTES + ((c ^ rsw) << 4),
                       gA + a_row_off + kk + c * 8);
            cp_async16(b_smem_row + s * STAGE_BYTES + ((c ^ rsw) << 4),
                       gB + b_row_off + kk + c * 8);
        }
        cp_commit();
    }

    int smem_read = 0, smem_write = STAGES - 1;

    for (int it = 0; it < NITER; ++it) {
        cp_wait1();
        __syncthreads();

        // issue loads for it + STAGES - 1
        const int itn = it + STAGES - 1;
        if (itn < NITER) {
            const int kk = itn * BK;
            #pragma unroll
            for (int j = 0; j < 4; j++) {
                int c = ldcb + j;
                cp_async16(a_smem_row + smem_write * STAGE_BYTES + ((c ^ rsw) << 4),
                           gA + a_row_off + kk + c * 8);
                cp_async16(b_smem_row + smem_write * STAGE_BYTES + ((c ^ rsw) << 4),
                           gB + b_row_off + kk + c * 8);
            }
        }
        cp_commit();

        // --- compute current stage in 2 mt-groups (register-pressure control).
        // Within a group: chain 4 k-steps (K=64) in f16 accumulators, then fold.
        const uint32_t aBase = sb + smem_read * STAGE_BYTES;
        const uint32_t bBase = aBase + 16384;
        const int lr = lane & 15;
        const int lc = lane >> 4;

        #pragma unroll
        for (int g = 0; g < 2; g++) {
            uint32_t cc[2][4][2];          // f16x2 chain accs: 2 mt x 4 nt x 2 regs
            #pragma unroll
            for (int m2 = 0; m2 < 2; m2++)
                #pragma unroll
                for (int nt = 0; nt < 4; nt++) {
                    cc[m2][nt][0] = 0u; cc[m2][nt][1] = 0u;
                }

            #pragma unroll
            for (int ks = 0; ks < 4; ks++) {
                const int c = ks * 2 + lc;
                uint32_t a[2][4];
                #pragma unroll
                for (int m2 = 0; m2 < 2; m2++) {
                    int r = wm * 64 + (g * 2 + m2) * 16 + lr;
                    uint32_t ad = aBase + r * 128 + (((c ^ (r & 7))) << 4);
                    ldmatrix_x4(a[m2][0], a[m2][1], a[m2][2], a[m2][3], ad);
                }
                uint32_t b[4][2];
                #pragma unroll
                for (int nh = 0; nh < 2; nh++) {
                    int r = wn * 32 + nh * 16 + lr;
                    uint32_t bd = bBase + r * 128 + (((c ^ (r & 7))) << 4);
                    uint32_t t0, t1, t2, t3;
                    ldmatrix_x4(t0, t1, t2, t3, bd);
                    b[nh * 2 + 0][0] = t0; b[nh * 2 + 0][1] = t2;
                    b[nh * 2 + 1][0] = t1; b[nh * 2 + 1][1] = t3;
                }
                #pragma unroll
                for (int m2 = 0; m2 < 2; m2++)
                    #pragma unroll
                    for (int nt = 0; nt < 4; nt++)
                        mma_f16acc(cc[m2][nt][0], cc[m2][nt][1],
                                   a[m2][0], a[m2][1], a[m2][2], a[m2][3],
                                   b[nt][0], b[nt][1]);
            }

            // fold f16 chains into f32 accumulators
            #pragma unroll
            for (int m2 = 0; m2 < 2; m2++) {
                const int mt = g * 2 + m2;
                #pragma unroll
                for (int nt = 0; nt < 4; nt++) {
                    float2 f0 = __half22float2(*reinterpret_cast<__half2*>(&cc[m2][nt][0]));
                    float2 f1 = __half22float2(*reinterpret_cast<__half2*>(&cc[m2][nt][1]));
                    acc[mt][nt][0] += f0.x;
                    acc[mt][nt][1] += f0.y;
                    acc[mt][nt][2] += f1.x;
                    acc[mt][nt][3] += f1.y;
                }
            }
        }

        smem_read = (smem_read + 1 == STAGES) ? 0 : smem_read + 1;
        smem_write = (smem_write + 1 == STAGES) ? 0 : smem_write + 1;
    }

    // --- epilogue: out = acc*half + bias ---
    const int mbase = m0 + wm * 64;
    const int nbase = n0 + wn * 32;
    const int lrow = lane >> 2;
    const int lcol = (lane & 3) * 2;

    #pragma unroll
    for (int nt = 0; nt < 4; nt++) {
        const int col = nbase + nt * 8 + lcol;
        const float bx = __ldg(&bias[col]);
        const float by = __ldg(&bias[col + 1]);
        #pragma unroll
        for (int mt = 0; mt < 4; mt++) {
            const int row0 = mbase + mt * 16 + lrow;
            float2 v0, v1;
            v0.x = acc[mt][nt][0] * halfv + bx;
            v0.y = acc[mt][nt][1] * halfv + by;
            v1.x = acc[mt][nt][2] * halfv + bx;
            v1.y = acc[mt][nt][3] * halfv + by;
            *reinterpret_cast<float2*>(out + (size_t)row0 * NDIM + col) = v0;
            *reinterpret_cast<float2*>(out + (size_t)(row0 + 8) * NDIM + col) = v1;
        }
    }
}

// ---------------------------------------------------------------------------
// Host launch
// ---------------------------------------------------------------------------
extern "C" void kernel_launch(void* const* d_in, const int* in_sizes, int n_in,
                              void* d_out, int out_size) {
    // Identify inputs by size: x=67108864, w=16777216, bias=4096
    const float* x = nullptr; const float* w = nullptr; const float* bias = nullptr;
    for (int i = 0; i < n_in; i++) {
        if (in_sizes[i] == MDIM * KDIM)      x = (const float*)d_in[i];
        else if (in_sizes[i] == NDIM * KDIM) w = (const float*)d_in[i];
        else if (in_sizes[i] == NDIM)        bias = (const float*)d_in[i];
    }
    float* out = (float*)d_out;

    const float halfv = (float)((pow(2.0, 1.58) - 1.0) * 0.5);

    // Prep: gamma (deterministic), W -> ternary fp16, X -> fp16
    k_reduce1<<<4096, 256>>>(w);
    k_reduce2<<<1, 256>>>();
    k_quantw<<<(NDIM * KDIM) / (256 * 4), 256>>>(w, halfv);
    k_convx<<<(MDIM * KDIM) / (256 * 4), 256>>>(x);

    // GEMM
    static bool attr_set = false;
    if (!attr_set) {
        cudaFuncSetAttribute(k_gemm, cudaFuncAttributeMaxDynamicSharedMemorySize, SMEM_BYTES);
        attr_set = true;
    }
    dim3 grid((MDIM / BM) * (NDIM / BN));   // 128 * 32 = 4096 CTAs
    k_gemm<<<grid, 256, SMEM_BYTES>>>(bias, out, halfv);
}

// round 12
// speedup vs baseline: 1.3118x; 1.2044x over previous
#include <cuda_runtime.h>
#include <cuda_fp16.h>
#include <cstdint>
#include <cstddef>
#include <math.h>

// ---------------------------------------------------------------------------
// Problem dims (fixed by the dataset)
// ---------------------------------------------------------------------------
#define MDIM 16384          // B*S = 8*2048
#define NDIM 4096           // D_OUT
#define KDIM 4096           // D_IN

#define BM 128
#define BN 128
#define BK 64               // fp16 elements per stage (128 bytes per row)
#define STAGES 3
#define NITER (KDIM / BK)   // 64

// Stage layout: [A 16KB][B 16KB] per stage, 3 stages = 96KB dynamic smem
#define STAGE_BYTES 32768
#define SMEM_BYTES (STAGES * STAGE_BYTES)

// ---------------------------------------------------------------------------
// Device scratch (static globals: no allocation in kernel_launch)
// ---------------------------------------------------------------------------
__device__ __half g_A[(size_t)MDIM * KDIM];   // 128 MB: x as fp16 (single plane)
__device__ __half g_B[(size_t)NDIM * KDIM];   // 32 MB: ternary weights {-1,0,1}
__device__ double g_partial[4096];
__device__ float  g_gamma;

// ---------------------------------------------------------------------------
// PTX helpers (family-portable: cp.async / ldmatrix / mma.sync only)
// ---------------------------------------------------------------------------
__device__ __forceinline__ uint32_t s2u(const void* p) {
    return (uint32_t)__cvta_generic_to_shared(p);
}

__device__ __forceinline__ void cp_async16(uint32_t smem_dst, const void* gmem_src) {
    asm volatile("cp.async.cg.shared.global [%0], [%1], 16;"
                 :: "r"(smem_dst), "l"(gmem_src));
}
__device__ __forceinline__ void cp_commit() {
    asm volatile("cp.async.commit_group;");
}
__device__ __forceinline__ void cp_wait1() {
    asm volatile("cp.async.wait_group 1;");
}

__device__ __forceinline__ void ldmatrix_x4(uint32_t& r0, uint32_t& r1, uint32_t& r2,
                                            uint32_t& r3, uint32_t addr) {
    asm volatile("ldmatrix.sync.aligned.m8n8.x4.shared.b16 {%0,%1,%2,%3}, [%4];"
                 : "=r"(r0), "=r"(r1), "=r"(r2), "=r"(r3) : "r"(addr));
}

__device__ __forceinline__ void mma_f16(float& c0, float& c1, float& c2, float& c3,
                                        uint32_t a0, uint32_t a1, uint32_t a2, uint32_t a3,
                                        uint32_t b0, uint32_t b1) {
    asm volatile("mma.sync.aligned.m16n8k16.row.col.f32.f16.f16.f32 "
                 "{%0,%1,%2,%3}, {%4,%5,%6,%7}, {%8,%9}, {%0,%1,%2,%3};"
                 : "+f"(c0), "+f"(c1), "+f"(c2), "+f"(c3)
                 : "r"(a0), "r"(a1), "r"(a2), "r"(a3), "r"(b0), "r"(b1));
}

// ---------------------------------------------------------------------------
// Prep kernels
// ---------------------------------------------------------------------------
// gamma = mean|w|, deterministic two-stage double tree.
__global__ void k_reduce1(const float* __restrict__ w) {
    __shared__ double sdata[256];
    const float* p = w + (size_t)blockIdx.x * 4096;
    double s = 0.0;
    for (int i = threadIdx.x; i < 4096; i += 256) s += (double)fabsf(p[i]);
    sdata[threadIdx.x] = s;
    __syncthreads();
    for (int st = 128; st > 0; st >>= 1) {
        if (threadIdx.x < st) sdata[threadIdx.x] += sdata[threadIdx.x + st];
        __syncthreads();
    }
    if (threadIdx.x == 0) g_partial[blockIdx.x] = sdata[0];
}
__global__ void k_reduce2() {
    __shared__ double sdata[256];
    double s = 0.0;
    for (int i = threadIdx.x; i < 4096; i += 256) s += g_partial[i];
    sdata[threadIdx.x] = s;
    __syncthreads();
    for (int st = 128; st > 0; st >>= 1) {
        if (threadIdx.x < st) sdata[threadIdx.x] += sdata[threadIdx.x + st];
        __syncthreads();
    }
    if (threadIdx.x == 0) g_gamma = (float)(sdata[0] / 16777216.0);
}

// Quantize weights to ternary fp16 {-1,0,1} (the *h scale applied in epilogue).
// Exact reference op order: clip(round(w / (gamma+eps) * half), -half, half) = half*t.
__global__ void k_quantw(const float* __restrict__ w, float halfv) {
    size_t i4 = (size_t)blockIdx.x * blockDim.x + threadIdx.x;   // float4 index, exact grid
    float gamma = g_gamma;
    float denom = gamma + 1e-8f;
    float4 v = reinterpret_cast<const float4*>(w)[i4];
    __half o[4];
    float q;
    q = rintf(v.x / denom * halfv); o[0] = __float2half(fminf(fmaxf(q, -1.0f), 1.0f));
    q = rintf(v.y / denom * halfv); o[1] = __float2half(fminf(fmaxf(q, -1.0f), 1.0f));
    q = rintf(v.z / denom * halfv); o[2] = __float2half(fminf(fmaxf(q, -1.0f), 1.0f));
    q = rintf(v.w / denom * halfv); o[3] = __float2half(fminf(fmaxf(q, -1.0f), 1.0f));
    reinterpret_cast<uint64_t*>(g_B)[i4] = *reinterpret_cast<uint64_t*>(o);
}

// Convert x (fp32) -> fp16 plane. 2 float4 per thread, warp-coalesced stride.
__global__ void k_convx(const float* __restrict__ x) {
    const size_t base = (size_t)blockIdx.x * 512 + threadIdx.x;  // float4 index
    #pragma unroll
    for (int j = 0; j < 2; j++) {
        size_t i4 = base + j * 256;
        float4 v = reinterpret_cast<const float4*>(x)[i4];
        __half o[4];
        o[0] = __float2half(v.x);
        o[1] = __float2half(v.y);
        o[2] = __float2half(v.z);
        o[3] = __float2half(v.w);
        reinterpret_cast<uint64_t*>(g_A)[i4] = *reinterpret_cast<uint64_t*>(o);
    }
}

// ---------------------------------------------------------------------------
// Main GEMM: mma.sync fp16, BM=128 x BN=128 x BK=64, cp.async 3-stage pipeline
// 8 warps: 2 (m) x 4 (n); warp tile 64x32; out = acc*half + bias
// ---------------------------------------------------------------------------
__global__ void __launch_bounds__(256, 2) k_gemm(
    const float* __restrict__ bias,
    float* __restrict__ out,
    float halfv)
{
    extern __shared__ char smem[];
    const uint32_t sb = s2u(smem);
    const int tid = threadIdx.x;
    const int wid = tid >> 5;
    const int lane = tid & 31;
    const int wm = wid >> 2;         // 0..1
    const int wn = wid & 3;          // 0..3

    const int nt_blk = blockIdx.x & 31;      // nt fastest: B tile reuse in L2
    const int mt_blk = blockIdx.x >> 5;
    const int m0 = mt_blk * BM;
    const int n0 = nt_blk * BN;

    const __half* gA = g_A;
    const __half* gB = g_B;

    // --- per-thread cp.async mapping: 2 threads per row, 4x16B chunks each ---
    const int ldrow = tid >> 1;               // 0..127
    const int ldcb  = (tid & 1) * 4;          // chunk base 0 or 4
    const size_t a_row_off = (size_t)(m0 + ldrow) * KDIM;
    const size_t b_row_off = (size_t)(n0 + ldrow) * KDIM;
    const uint32_t a_smem_row = sb + ldrow * 128;
    const uint32_t b_smem_row = sb + 16384 + ldrow * 128;
    const int rsw = ldrow & 7;

    float acc[4][4][4];
    #pragma unroll
    for (int i = 0; i < 4; i++)
        #pragma unroll
        for (int j = 0; j < 4; j++)
            #pragma unroll
            for (int k = 0; k < 4; k++) acc[i][j][k] = 0.0f;

    // --- prologue: issue stages 0..STAGES-2 ---
    #pragma unroll
    for (int s = 0; s < STAGES - 1; s++) {
        const int kk = s * BK;
        #pragma unroll
        for (int j = 0; j < 4; j++) {
            int c = ldcb + j;
            cp_async16(a_smem_row + s * STAGE_BYTES + ((c ^ rsw) << 4),
                       gA + a_row_off + kk + c * 8);
            cp_async16(b_smem_row + s * STAGE_BYTES + ((c ^ rsw) << 4),
                       gB + b_row_off + kk + c * 8);
        }
        cp_commit();
    }

    int smem_read = 0, smem_write = STAGES - 1;

    const int lr = lane & 15;
    const int lc = lane >> 4;

    for (int it = 0; it < NITER; ++it) {
        cp_wait1();
        __syncthreads();

        const uint32_t aBase = sb + smem_read * STAGE_BYTES;
        const uint32_t bBase = aBase + 16384;

        // --- hoist ks=0 fragment loads so the HMMA chain starts before the
        //     LSU gets occupied by the next-stage cp.async burst ---
        uint32_t a[4][4];
        uint32_t b[4][2];
        {
            const int c = lc;   // ks = 0
            #pragma unroll
            for (int mt = 0; mt < 4; mt++) {
                int r = wm * 64 + mt * 16 + lr;
                uint32_t ad = aBase + r * 128 + (((c ^ (r & 7))) << 4);
                ldmatrix_x4(a[mt][0], a[mt][1], a[mt][2], a[mt][3], ad);
            }
            #pragma unroll
            for (int nh = 0; nh < 2; nh++) {
                int r = wn * 32 + nh * 16 + lr;
                uint32_t bd = bBase + r * 128 + (((c ^ (r & 7))) << 4);
                uint32_t t0, t1, t2, t3;
                ldmatrix_x4(t0, t1, t2, t3, bd);
                b[nh * 2 + 0][0] = t0; b[nh * 2 + 0][1] = t2;
                b[nh * 2 + 1][0] = t1; b[nh * 2 + 1][1] = t3;
            }
        }

        // issue loads for it + STAGES - 1
        const int itn = it + STAGES - 1;
        if (itn < NITER) {
            const int kk = itn * BK;
            #pragma unroll
            for (int j = 0; j < 4; j++) {
                int c = ldcb + j;
                cp_async16(a_smem_row + smem_write * STAGE_BYTES + ((c ^ rsw) << 4),
                           gA + a_row_off + kk + c * 8);
                cp_async16(b_smem_row + smem_write * STAGE_BYTES + ((c ^ rsw) << 4),
                           gB + b_row_off + kk + c * 8);
            }
        }
        cp_commit();

        // --- compute: 4 k-steps of k16; frags for ks already in regs ---
        #pragma unroll
        for (int ks = 0; ks < 4; ks++) {
            #pragma unroll
            for (int mt = 0; mt < 4; mt++)
                #pragma unroll
                for (int nt = 0; nt < 4; nt++)
                    mma_f16(acc[mt][nt][0], acc[mt][nt][1], acc[mt][nt][2], acc[mt][nt][3],
                            a[mt][0], a[mt][1], a[mt][2], a[mt][3],
                            b[nt][0], b[nt][1]);

            // load fragments for next k-step (overlaps with HMMA chain above)
            if (ks < 3) {
                const int c = (ks + 1) * 2 + lc;
                #pragma unroll
                for (int mt = 0; mt < 4; mt++) {
                    int r = wm * 64 + mt * 16 + lr;
                    uint32_t ad = aBase + r * 128 + (((c ^ (r & 7))) << 4);
                    ldmatrix_x4(a[mt][0], a[mt][1], a[mt][2], a[mt][3], ad);
                }
                #pragma unroll
                for (int nh = 0; nh < 2; nh++) {
                    int r = wn * 32 + nh * 16 + lr;
                    uint32_t bd = bBase + r * 128 + (((c ^ (r & 7))) << 4);
                    uint32_t t0, t1, t2, t3;
                    ldmatrix_x4(t0, t1, t2, t3, bd);
                    b[nh * 2 + 0][0] = t0; b[nh * 2 + 0][1] = t2;
                    b[nh * 2 + 1][0] = t1; b[nh * 2 + 1][1] = t3;
                }
            }
        }

        smem_read = (smem_read + 1 == STAGES) ? 0 : smem_read + 1;
        smem_write = (smem_write + 1 == STAGES) ? 0 : smem_write + 1;
    }

    // --- epilogue: out = acc*half + bias ---
    const int mbase = m0 + wm * 64;
    const int nbase = n0 + wn * 32;
    const int lrow = lane >> 2;
    const int lcol = (lane & 3) * 2;

    #pragma unroll
    for (int nt = 0; nt < 4; nt++) {
        const int col = nbase + nt * 8 + lcol;
        const float bx = __ldg(&bias[col]);
        const float by = __ldg(&bias[col + 1]);
        #pragma unroll
        for (int mt = 0; mt < 4; mt++) {
            const int row0 = mbase + mt * 16 + lrow;
            float2 v0, v1;
            v0.x = acc[mt][nt][0] * halfv + bx;
            v0.y = acc[mt][nt][1] * halfv + by;
            v1.x = acc[mt][nt][2] * halfv + bx;
            v1.y = acc[mt][nt][3] * halfv + by;
            *reinterpret_cast<float2*>(out + (size_t)row0 * NDIM + col) = v0;
            *reinterpret_cast<float2*>(out + (size_t)(row0 + 8) * NDIM + col) = v1;
        }
    }
}

// ---------------------------------------------------------------------------
// Host launch
// ---------------------------------------------------------------------------
extern "C" void kernel_launch(void* const* d_in, const int* in_sizes, int n_in,
                              void* d_out, int out_size) {
    // Identify inputs by size: x=67108864, w=16777216, bias=4096
    const float* x = nullptr; const float* w = nullptr; const float* bias = nullptr;
    for (int i = 0; i < n_in; i++) {
        if (in_sizes[i] == MDIM * KDIM)      x = (const float*)d_in[i];
        else if (in_sizes[i] == NDIM * KDIM) w = (const float*)d_in[i];
        else if (in_sizes[i] == NDIM)        bias = (const float*)d_in[i];
    }
    float* out = (float*)d_out;

    const float halfv = (float)((pow(2.0, 1.58) - 1.0) * 0.5);

    // Prep: gamma (deterministic), W -> ternary fp16, X -> fp16
    k_reduce1<<<4096, 256>>>(w);
    k_reduce2<<<1, 256>>>();
    k_quantw<<<(NDIM * KDIM) / (256 * 4), 256>>>(w, halfv);
    k_convx<<<(MDIM * KDIM) / (256 * 4 * 2), 256>>>(x);

    // GEMM
    static bool attr_set = false;
    if (!attr_set) {
        cudaFuncSetAttribute(k_gemm, cudaFuncAttributeMaxDynamicSharedMemorySize, SMEM_BYTES);
        attr_set = true;
    }
    dim3 grid((MDIM / BM) * (NDIM / BN));   // 128 * 32 = 4096 CTAs
    k_gemm<<<grid, 256, SMEM_BYTES>>>(bias, out, halfv);
}

// round 15
// speedup vs baseline: 1.3193x; 1.0057x over previous
#include <cuda_runtime.h>
#include <cuda_fp16.h>
#include <cstdint>
#include <cstddef>
#include <math.h>

// ---------------------------------------------------------------------------
// Problem dims (fixed by the dataset)
// ---------------------------------------------------------------------------
#define MDIM 16384          // B*S = 8*2048
#define NDIM 4096           // D_OUT
#define KDIM 4096           // D_IN

#define BM 128
#define BN 128
#define BK 64               // fp16 elements per stage (128 bytes per row)
#define STAGES 3
#define NITER (KDIM / BK)   // 64

// Stage layout: [A 16KB][B 16KB] per stage, 3 stages = 96KB dynamic smem
#define STAGE_BYTES 32768
#define SMEM_BYTES (STAGES * STAGE_BYTES)

// ---------------------------------------------------------------------------
// Device scratch (static globals: no allocation in kernel_launch)
// ---------------------------------------------------------------------------
__device__ __half g_A[(size_t)MDIM * KDIM];   // 128 MB: x as fp16 (single plane)
__device__ __half g_B[(size_t)NDIM * KDIM];   // 32 MB: ternary weights {-1,0,1}
__device__ double g_partial[4096];
__device__ float  g_gamma;

// ---------------------------------------------------------------------------
// PTX helpers (family-portable: cp.async / ldmatrix / mma.sync only)
// ---------------------------------------------------------------------------
__device__ __forceinline__ uint32_t s2u(const void* p) {
    return (uint32_t)__cvta_generic_to_shared(p);
}

__device__ __forceinline__ void cp_async16(uint32_t smem_dst, const void* gmem_src) {
    asm volatile("cp.async.cg.shared.global [%0], [%1], 16;"
                 :: "r"(smem_dst), "l"(gmem_src));
}
__device__ __forceinline__ void cp_commit() {
    asm volatile("cp.async.commit_group;");
}
__device__ __forceinline__ void cp_wait1() {
    asm volatile("cp.async.wait_group 1;");
}

__device__ __forceinline__ void ldmatrix_x4(uint32_t& r0, uint32_t& r1, uint32_t& r2,
                                            uint32_t& r3, uint32_t addr) {
    asm volatile("ldmatrix.sync.aligned.m8n8.x4.shared.b16 {%0,%1,%2,%3}, [%4];"
                 : "=r"(r0), "=r"(r1), "=r"(r2), "=r"(r3) : "r"(addr));
}

__device__ __forceinline__ void mma_f16(float& c0, float& c1, float& c2, float& c3,
                                        uint32_t a0, uint32_t a1, uint32_t a2, uint32_t a3,
                                        uint32_t b0, uint32_t b1) {
    asm volatile("mma.sync.aligned.m16n8k16.row.col.f32.f16.f16.f32 "
                 "{%0,%1,%2,%3}, {%4,%5,%6,%7}, {%8,%9}, {%0,%1,%2,%3};"
                 : "+f"(c0), "+f"(c1), "+f"(c2), "+f"(c3)
                 : "r"(a0), "r"(a1), "r"(a2), "r"(a3), "r"(b0), "r"(b1));
}

// ---------------------------------------------------------------------------
// Prep kernels
// ---------------------------------------------------------------------------
// gamma = mean|w|, deterministic two-stage double tree. float4 loads.
__global__ void k_reduce1(const float* __restrict__ w) {
    __shared__ double sdata[256];
    const float4* p = reinterpret_cast<const float4*>(w + (size_t)blockIdx.x * 4096);
    double s = 0.0;
    for (int i = threadIdx.x; i < 1024; i += 256) {
        float4 v = p[i];
        s += (double)fabsf(v.x) + (double)fabsf(v.y)
           + (double)fabsf(v.z) + (double)fabsf(v.w);
    }
    sdata[threadIdx.x] = s;
    __syncthreads();
    for (int st = 128; st > 0; st >>= 1) {
        if (threadIdx.x < st) sdata[threadIdx.x] += sdata[threadIdx.x + st];
        __syncthreads();
    }
    if (threadIdx.x == 0) g_partial[blockIdx.x] = sdata[0];
}
__global__ void k_reduce2() {
    __shared__ double sdata[256];
    double s = 0.0;
    for (int i = threadIdx.x; i < 4096; i += 256) s += g_partial[i];
    sdata[threadIdx.x] = s;
    __syncthreads();
    for (int st = 128; st > 0; st >>= 1) {
        if (threadIdx.x < st) sdata[threadIdx.x] += sdata[threadIdx.x + st];
        __syncthreads();
    }
    if (threadIdx.x == 0) g_gamma = (float)(sdata[0] / 16777216.0);
}

// Quantize weights to ternary fp16 {-1,0,1} (the *h scale applied in epilogue).
// Exact reference op order: clip(round(w / (gamma+eps) * half), -half, half) = half*t.
// 2 float4 per thread, warp-coalesced stride.
__global__ void k_quantw(const float* __restrict__ w, float halfv) {
    const size_t base = (size_t)blockIdx.x * 512 + threadIdx.x;  // float4 index
    const float denom = g_gamma + 1e-8f;
    #pragma unroll
    for (int j = 0; j < 2; j++) {
        size_t i4 = base + j * 256;
        float4 v = reinterpret_cast<const float4*>(w)[i4];
        __half o[4];
        float q;
        q = rintf(v.x / denom * halfv); o[0] = __float2half(fminf(fmaxf(q, -1.0f), 1.0f));
        q = rintf(v.y / denom * halfv); o[1] = __float2half(fminf(fmaxf(q, -1.0f), 1.0f));
        q = rintf(v.z / denom * halfv); o[2] = __float2half(fminf(fmaxf(q, -1.0f), 1.0f));
        q = rintf(v.w / denom * halfv); o[3] = __float2half(fminf(fmaxf(q, -1.0f), 1.0f));
        reinterpret_cast<uint64_t*>(g_B)[i4] = *reinterpret_cast<uint64_t*>(o);
    }
}

// Convert x (fp32) -> fp16 plane. 2 float4 per thread, warp-coalesced stride.
__global__ void k_convx(const float* __restrict__ x) {
    const size_t base = (size_t)blockIdx.x * 512 + threadIdx.x;  // float4 index
    #pragma unroll
    for (int j = 0; j < 2; j++) {
        size_t i4 = base + j * 256;
        float4 v = reinterpret_cast<const float4*>(x)[i4];
        __half o[4];
        o[0] = __float2half(v.x);
        o[1] = __float2half(v.y);
        o[2] = __float2half(v.z);
        o[3] = __float2half(v.w);
        reinterpret_cast<uint64_t*>(g_A)[i4] = *reinterpret_cast<uint64_t*>(o);
    }
}

// ---------------------------------------------------------------------------
// Main GEMM: mma.sync fp16, BM=128 x BN=128 x BK=64, cp.async 3-stage pipeline
// 8 warps: 2 (m) x 4 (n); warp tile 64x32; out = acc*half + bias
// (byte-identical to the R12 winner)
// ---------------------------------------------------------------------------
__global__ void __launch_bounds__(256, 2) k_gemm(
    const float* __restrict__ bias,
    float* __restrict__ out,
    float halfv)
{
    extern __shared__ char smem[];
    const uint32_t sb = s2u(smem);
    const int tid = threadIdx.x;
    const int wid = tid >> 5;
    const int lane = tid & 31;
    const int wm = wid >> 2;         // 0..1
    const int wn = wid & 3;          // 0..3

    const int nt_blk = blockIdx.x & 31;      // nt fastest: B tile reuse in L2
    const int mt_blk = blockIdx.x >> 5;
    const int m0 = mt_blk * BM;
    const int n0 = nt_blk * BN;

    const __half* gA = g_A;
    const __half* gB = g_B;

    // --- per-thread cp.async mapping: 2 threads per row, 4x16B chunks each ---
    const int ldrow = tid >> 1;               // 0..127
    const int ldcb  = (tid & 1) * 4;          // chunk base 0 or 4
    const size_t a_row_off = (size_t)(m0 + ldrow) * KDIM;
    const size_t b_row_off = (size_t)(n0 + ldrow) * KDIM;
    const uint32_t a_smem_row = sb + ldrow * 128;
    const uint32_t b_smem_row = sb + 16384 + ldrow * 128;
    const int rsw = ldrow & 7;

    float acc[4][4][4];
    #pragma unroll
    for (int i = 0; i < 4; i++)
        #pragma unroll
        for (int j = 0; j < 4; j++)
            #pragma unroll
            for (int k = 0; k < 4; k++) acc[i][j][k] = 0.0f;

    // --- prologue: issue stages 0..STAGES-2 ---
    #pragma unroll
    for (int s = 0; s < STAGES - 1; s++) {
        const int kk = s * BK;
        #pragma unroll
        for (int j = 0; j < 4; j++) {
            int c = ldcb + j;
            cp_async16(a_smem_row + s * STAGE_BYTES + ((c ^ rsw) << 4),
                       gA + a_row_off + kk + c * 8);
            cp_async16(b_smem_row + s * STAGE_BYTES + ((c ^ rsw) << 4),
                       gB + b_row_off + kk + c * 8);
        }
        cp_commit();
    }

    int smem_read = 0, smem_write = STAGES - 1;

    const int lr = lane & 15;
    const int lc = lane >> 4;

    for (int it = 0; it < NITER; ++it) {
        cp_wait1();
        __syncthreads();

        const uint32_t aBase = sb + smem_read * STAGE_BYTES;
        const uint32_t bBase = aBase + 16384;

        // --- hoist ks=0 fragment loads so the HMMA chain starts before the
        //     LSU gets occupied by the next-stage cp.async burst ---
        uint32_t a[4][4];
        uint32_t b[4][2];
        {
            const int c = lc;   // ks = 0
            #pragma unroll
            for (int mt = 0; mt < 4; mt++) {
                int r = wm * 64 + mt * 16 + lr;
                uint32_t ad = aBase + r * 128 + (((c ^ (r & 7))) << 4);
                ldmatrix_x4(a[mt][0], a[mt][1], a[mt][2], a[mt][3], ad);
            }
            #pragma unroll
            for (int nh = 0; nh < 2; nh++) {
                int r = wn * 32 + nh * 16 + lr;
                uint32_t bd = bBase + r * 128 + (((c ^ (r & 7))) << 4);
                uint32_t t0, t1, t2, t3;
                ldmatrix_x4(t0, t1, t2, t3, bd);
                b[nh * 2 + 0][0] = t0; b[nh * 2 + 0][1] = t2;
                b[nh * 2 + 1][0] = t1; b[nh * 2 + 1][1] = t3;
            }
        }

        // issue loads for it + STAGES - 1
        const int itn = it + STAGES - 1;
        if (itn < NITER) {
            const int kk = itn * BK;
            #pragma unroll
            for (int j = 0; j < 4; j++) {
                int c = ldcb + j;
                cp_async16(a_smem_row + smem_write * STAGE_BYTES + ((c ^ rsw) << 4),
                           gA + a_row_off + kk + c * 8);
                cp_async16(b_smem_row + smem_write * STAGE_BYTES + ((c ^ rsw) << 4),
                           gB + b_row_off + kk + c * 8);
            }
        }
        cp_commit();

        // --- compute: 4 k-steps of k16; frags for ks already in regs ---
        #pragma unroll
        for (int ks = 0; ks < 4; ks++) {
            #pragma unroll
            for (int mt = 0; mt < 4; mt++)
                #pragma unroll
                for (int nt = 0; nt < 4; nt++)
                    mma_f16(acc[mt][nt][0], acc[mt][nt][1], acc[mt][nt][2], acc[mt][nt][3],
                            a[mt][0], a[mt][1], a[mt][2], a[mt][3],
                            b[nt][0], b[nt][1]);

            // load fragments for next k-step (overlaps with HMMA chain above)
            if (ks < 3) {
                const int c = (ks + 1) * 2 + lc;
                #pragma unroll
                for (int mt = 0; mt < 4; mt++) {
                    int r = wm * 64 + mt * 16 + lr;
                    uint32_t ad = aBase + r * 128 + (((c ^ (r & 7))) << 4);
                    ldmatrix_x4(a[mt][0], a[mt][1], a[mt][2], a[mt][3], ad);
                }
                #pragma unroll
                for (int nh = 0; nh < 2; nh++) {
                    int r = wn * 32 + nh * 16 + lr;
                    uint32_t bd = bBase + r * 128 + (((c ^ (r & 7))) << 4);
                    uint32_t t0, t1, t2, t3;
                    ldmatrix_x4(t0, t1, t2, t3, bd);
                    b[nh * 2 + 0][0] = t0; b[nh * 2 + 0][1] = t2;
                    b[nh * 2 + 1][0] = t1; b[nh * 2 + 1][1] = t3;
                }
            }
        }

        smem_read = (smem_read + 1 == STAGES) ? 0 : smem_read + 1;
        smem_write = (smem_write + 1 == STAGES) ? 0 : smem_write + 1;
    }

    // --- epilogue: out = acc*half + bias ---
    const int mbase = m0 + wm * 64;
    const int nbase = n0 + wn * 32;
    const int lrow = lane >> 2;
    const int lcol = (lane & 3) * 2;

    #pragma unroll
    for (int nt = 0; nt < 4; nt++) {
        const int col = nbase + nt * 8 + lcol;
        const float bx = __ldg(&bias[col]);
        const float by = __ldg(&bias[col + 1]);
        #pragma unroll
        for (int mt = 0; mt < 4; mt++) {
            const int row0 = mbase + mt * 16 + lrow;
            float2 v0, v1;
            v0.x = acc[mt][nt][0] * halfv + bx;
            v0.y = acc[mt][nt][1] * halfv + by;
            v1.x = acc[mt][nt][2] * halfv + bx;
            v1.y = acc[mt][nt][3] * halfv + by;
            *reinterpret_cast<float2*>(out + (size_t)row0 * NDIM + col) = v0;
            *reinterpret_cast<float2*>(out + (size_t)(row0 + 8) * NDIM + col) = v1;
        }
    }
}

// ---------------------------------------------------------------------------
// Host launch: fork the w-chain onto a second stream so it overlaps k_convx.
// Streams/events are created on the FIRST call (which the harness runs
// uncaptured for correctness) and reused inside graph capture thereafter —
// fork/join via events on the legacy stream is capture-legal.
// ---------------------------------------------------------------------------
extern "C" void kernel_launch(void* const* d_in, const int* in_sizes, int n_in,
                              void* d_out, int out_size) {
    // Identify inputs by size: x=67108864, w=16777216, bias=4096
    const float* x = nullptr; const float* w = nullptr; const float* bias = nullptr;
    for (int i = 0; i < n_in; i++) {
        if (in_sizes[i] == MDIM * KDIM)      x = (const float*)d_in[i];
        else if (in_sizes[i] == NDIM * KDIM) w = (const float*)d_in[i];
        else if (in_sizes[i] == NDIM)        bias = (const float*)d_in[i];
    }
    float* out = (float*)d_out;

    const float halfv = (float)((pow(2.0, 1.58) - 1.0) * 0.5);

    static cudaStream_t s2 = nullptr;
    static cudaEvent_t evFork = nullptr, evJoin = nullptr;
    static bool attr_set = false;
    if (!attr_set) {
        cudaFuncSetAttribute(k_gemm, cudaFuncAttributeMaxDynamicSharedMemorySize, SMEM_BYTES);
        cudaStreamCreateWithFlags(&s2, cudaStreamNonBlocking);
        cudaEventCreateWithFlags(&evFork, cudaEventDisableTiming);
        cudaEventCreateWithFlags(&evJoin, cudaEventDisableTiming);
        attr_set = true;
    }

    // Fork: w-chain on s2, x-chain on the main (capture) stream.
    cudaEventRecord(evFork, 0);
    cudaStreamWaitEvent(s2, evFork, 0);

    k_reduce1<<<4096, 256, 0, s2>>>(w);
    k_reduce2<<<1, 256, 0, s2>>>();
    k_quantw<<<(NDIM * KDIM) / (256 * 4 * 2), 256, 0, s2>>>(w, halfv);
    cudaEventRecord(evJoin, s2);

    k_convx<<<(MDIM * KDIM) / (256 * 4 * 2), 256>>>(x);

    // Join: GEMM needs both g_A (main stream) and g_B (s2).
    cudaStreamWaitEvent(0, evJoin, 0);

    dim3 grid((MDIM / BM) * (NDIM / BN));   // 128 * 32 = 4096 CTAs
    k_gemm<<<grid, 256, SMEM_BYTES>>>(bias, out, halfv);
}

// round 17
// speedup vs baseline: 1.3276x; 1.0063x over previous
#include <cuda_runtime.h>
#include <cuda_fp16.h>
#include <cstdint>
#include <cstddef>
#include <math.h>

// ---------------------------------------------------------------------------
// Problem dims (fixed by the dataset)
// ---------------------------------------------------------------------------
#define MDIM 16384          // B*S = 8*2048
#define NDIM 4096           // D_OUT
#define KDIM 4096           // D_IN

#define BM 128
#define BN 128
#define BK 64               // fp16 elements per stage (128 bytes per row)
#define STAGES 3
#define NITER (KDIM / BK)   // 64

// Stage layout: [A 16KB][B 16KB] per stage, 3 stages = 96KB dynamic smem
#define STAGE_BYTES 32768
#define SMEM_BYTES (STAGES * STAGE_BYTES)

// ---------------------------------------------------------------------------
// Device scratch (static globals: no allocation in kernel_launch)
// ---------------------------------------------------------------------------
__device__ __half g_A[(size_t)MDIM * KDIM];   // 128 MB: x as fp16 (single plane)
__device__ __half g_B[(size_t)NDIM * KDIM];   // 32 MB: ternary weights {-1,0,1}
__device__ double g_partial[256];
__device__ float  g_gamma;

// ---------------------------------------------------------------------------
// PTX helpers (family-portable: cp.async / ldmatrix / mma.sync only)
// ---------------------------------------------------------------------------
__device__ __forceinline__ uint32_t s2u(const void* p) {
    return (uint32_t)__cvta_generic_to_shared(p);
}

__device__ __forceinline__ void cp_async16(uint32_t smem_dst, const void* gmem_src) {
    asm volatile("cp.async.cg.shared.global [%0], [%1], 16;"
                 :: "r"(smem_dst), "l"(gmem_src));
}
__device__ __forceinline__ void cp_commit() {
    asm volatile("cp.async.commit_group;");
}
__device__ __forceinline__ void cp_wait1() {
    asm volatile("cp.async.wait_group 1;");
}

__device__ __forceinline__ void ldmatrix_x4(uint32_t& r0, uint32_t& r1, uint32_t& r2,
                                            uint32_t& r3, uint32_t addr) {
    asm volatile("ldmatrix.sync.aligned.m8n8.x4.shared.b16 {%0,%1,%2,%3}, [%4];"
                 : "=r"(r0), "=r"(r1), "=r"(r2), "=r"(r3) : "r"(addr));
}

__device__ __forceinline__ void mma_f16(float& c0, float& c1, float& c2, float& c3,
                                        uint32_t a0, uint32_t a1, uint32_t a2, uint32_t a3,
                                        uint32_t b0, uint32_t b1) {
    asm volatile("mma.sync.aligned.m16n8k16.row.col.f32.f16.f16.f32 "
                 "{%0,%1,%2,%3}, {%4,%5,%6,%7}, {%8,%9}, {%0,%1,%2,%3};"
                 : "+f"(c0), "+f"(c1), "+f"(c2), "+f"(c3)
                 : "r"(a0), "r"(a1), "r"(a2), "r"(a3), "r"(b0), "r"(b1));
}

// ---------------------------------------------------------------------------
// Prep kernels
// ---------------------------------------------------------------------------
// sum|w| stage 1: 256 blocks, each over 65536 floats, deterministic tree.
__global__ void k_reduce1(const float* __restrict__ w) {
    __shared__ double sdata[256];
    const float4* p = reinterpret_cast<const float4*>(w) + (size_t)blockIdx.x * 16384;
    double s = 0.0;
    for (int i = threadIdx.x; i < 16384; i += 256) {
        float4 v = p[i];
        s += (double)fabsf(v.x) + (double)fabsf(v.y)
           + (double)fabsf(v.z) + (double)fabsf(v.w);
    }
    sdata[threadIdx.x] = s;
    __syncthreads();
    for (int st = 128; st > 0; st >>= 1) {
        if (threadIdx.x < st) sdata[threadIdx.x] += sdata[threadIdx.x + st];
        __syncthreads();
    }
    if (threadIdx.x == 0) g_partial[blockIdx.x] = sdata[0];
}

// Quantize weights to ternary fp16 {-1,0,1}; gamma computed in-block from the
// 256 partials (deterministic tree, same in every block) — kills the grid=1
// reduce2 kernel's latency on the critical path.
// Exact reference op order: clip(round(w / (gamma+eps) * half), -half, half) = half*t.
__global__ void k_quantw(const float* __restrict__ w, float halfv) {
    __shared__ double sdata[256];
    const int tid = threadIdx.x;
    sdata[tid] = g_partial[tid];
    __syncthreads();
    for (int st = 128; st > 0; st >>= 1) {
        if (tid < st) sdata[tid] += sdata[tid + st];
        __syncthreads();
    }
    const float denom = (float)(sdata[0] / 16777216.0) + 1e-8f;

    const size_t base = (size_t)blockIdx.x * 512 + tid;  // float4 index
    #pragma unroll
    for (int j = 0; j < 2; j++) {
        size_t i4 = base + j * 256;
        float4 v = reinterpret_cast<const float4*>(w)[i4];
        __half o[4];
        float q;
        q = rintf(v.x / denom * halfv); o[0] = __float2half(fminf(fmaxf(q, -1.0f), 1.0f));
        q = rintf(v.y / denom * halfv); o[1] = __float2half(fminf(fmaxf(q, -1.0f), 1.0f));
        q = rintf(v.z / denom * halfv); o[2] = __float2half(fminf(fmaxf(q, -1.0f), 1.0f));
        q = rintf(v.w / denom * halfv); o[3] = __float2half(fminf(fmaxf(q, -1.0f), 1.0f));
        reinterpret_cast<uint64_t*>(g_B)[i4] = *reinterpret_cast<uint64_t*>(o);
    }
}

// Convert x (fp32) -> fp16 plane for an M-chunk. 2 float4/thread, coalesced.
__global__ void k_convx(const float* __restrict__ x, size_t base4) {
    const size_t base = base4 + (size_t)blockIdx.x * 512 + threadIdx.x;  // float4 index
    #pragma unroll
    for (int j = 0; j < 2; j++) {
        size_t i4 = base + j * 256;
        float4 v = reinterpret_cast<const float4*>(x)[i4];
        __half o[4];
        o[0] = __float2half(v.x);
        o[1] = __float2half(v.y);
        o[2] = __float2half(v.z);
        o[3] = __float2half(v.w);
        reinterpret_cast<uint64_t*>(g_A)[i4] = *reinterpret_cast<uint64_t*>(o);
    }
}

// ---------------------------------------------------------------------------
// Main GEMM: mma.sync fp16, BM=128 x BN=128 x BK=64, cp.async 3-stage pipeline
// 8 warps: 2 (m) x 4 (n); warp tile 64x32; out = acc*half + bias
// (byte-identical to the R12 winner, plus an mt_off for M-split pipelining;
//  grid = 64 mt x 32 nt = 2048 CTAs per half)
// ---------------------------------------------------------------------------
__global__ void __launch_bounds__(256, 2) k_gemm(
    const float* __restrict__ bias,
    float* __restrict__ out,
    float halfv,
    int mt_off)
{
    extern __shared__ char smem[];
    const uint32_t sb = s2u(smem);
    const int tid = threadIdx.x;
    const int wid = tid >> 5;
    const int lane = tid & 31;
    const int wm = wid >> 2;         // 0..1
    const int wn = wid & 3;          // 0..3

    const int nt_blk = blockIdx.x & 31;      // nt fastest: B tile reuse in L2
    const int mt_blk = (blockIdx.x >> 5) + mt_off;
    const int m0 = mt_blk * BM;
    const int n0 = nt_blk * BN;

    const __half* gA = g_A;
    const __half* gB = g_B;

    // --- per-thread cp.async mapping: 2 threads per row, 4x16B chunks each ---
    const int ldrow = tid >> 1;               // 0..127
    const int ldcb  = (tid & 1) * 4;          // chunk base 0 or 4
    const size_t a_row_off = (size_t)(m0 + ldrow) * KDIM;
    const size_t b_row_off = (size_t)(n0 + ldrow) * KDIM;
    const uint32_t a_smem_row = sb + ldrow * 128;
    const uint32_t b_smem_row = sb + 16384 + ldrow * 128;
    const int rsw = ldrow & 7;

    float acc[4][4][4];
    #pragma unroll
    for (int i = 0; i < 4; i++)
        #pragma unroll
        for (int j = 0; j < 4; j++)
            #pragma unroll
            for (int k = 0; k < 4; k++) acc[i][j][k] = 0.0f;

    // --- prologue: issue stages 0..STAGES-2 ---
    #pragma unroll
    for (int s = 0; s < STAGES - 1; s++) {
        const int kk = s * BK;
        #pragma unroll
        for (int j = 0; j < 4; j++) {
            int c = ldcb + j;
            cp_async16(a_smem_row + s * STAGE_BYTES + ((c ^ rsw) << 4),
                       gA + a_row_off + kk + c * 8);
            cp_async16(b_smem_row + s * STAGE_BYTES + ((c ^ rsw) << 4),
                       gB + b_row_off + kk + c * 8);
        }
        cp_commit();
    }

    int smem_read = 0, smem_write = STAGES - 1;

    const int lr = lane & 15;
    const int lc = lane >> 4;

    for (int it = 0; it < NITER; ++it) {
        cp_wait1();
        __syncthreads();

        const uint32_t aBase = sb + smem_read * STAGE_BYTES;
        const uint32_t bBase = aBase + 16384;

        // --- hoist ks=0 fragment loads so the HMMA chain starts before the
        //     LSU gets occupied by the next-stage cp.async burst ---
        uint32_t a[4][4];
        uint32_t b[4][2];
        {
            const int c = lc;   // ks = 0
            #pragma unroll
            for (int mt = 0; mt < 4; mt++) {
                int r = wm * 64 + mt * 16 + lr;
                uint32_t ad = aBase + r * 128 + (((c ^ (r & 7))) << 4);
                ldmatrix_x4(a[mt][0], a[mt][1], a[mt][2], a[mt][3], ad);
            }
            #pragma unroll
            for (int nh = 0; nh < 2; nh++) {
                int r = wn * 32 + nh * 16 + lr;
                uint32_t bd = bBase + r * 128 + (((c ^ (r & 7))) << 4);
                uint32_t t0, t1, t2, t3;
                ldmatrix_x4(t0, t1, t2, t3, bd);
                b[nh * 2 + 0][0] = t0; b[nh * 2 + 0][1] = t2;
                b[nh * 2 + 1][0] = t1; b[nh * 2 + 1][1] = t3;
            }
        }

        // issue loads for it + STAGES - 1
        const int itn = it + STAGES - 1;
        if (itn < NITER) {
            const int kk = itn * BK;
            #pragma unroll
            for (int j = 0; j < 4; j++) {
                int c = ldcb + j;
                cp_async16(a_smem_row + smem_write * STAGE_BYTES + ((c ^ rsw) << 4),
                           gA + a_row_off + kk + c * 8);
                cp_async16(b_smem_row + smem_write * STAGE_BYTES + ((c ^ rsw) << 4),
                           gB + b_row_off + kk + c * 8);
            }
        }
        cp_commit();

        // --- compute: 4 k-steps of k16; frags for ks already in regs ---
        #pragma unroll
        for (int ks = 0; ks < 4; ks++) {
            #pragma unroll
            for (int mt = 0; mt < 4; mt++)
                #pragma unroll
                for (int nt = 0; nt < 4; nt++)
                    mma_f16(acc[mt][nt][0], acc[mt][nt][1], acc[mt][nt][2], acc[mt][nt][3],
                            a[mt][0], a[mt][1], a[mt][2], a[mt][3],
                            b[nt][0], b[nt][1]);

            // load fragments for next k-step (overlaps with HMMA chain above)
            if (ks < 3) {
                const int c = (ks + 1) * 2 + lc;
                #pragma unroll
                for (int mt = 0; mt < 4; mt++) {
                    int r = wm * 64 + mt * 16 + lr;
                    uint32_t ad = aBase + r * 128 + (((c ^ (r & 7))) << 4);
                    ldmatrix_x4(a[mt][0], a[mt][1], a[mt][2], a[mt][3], ad);
                }
                #pragma unroll
                for (int nh = 0; nh < 2; nh++) {
                    int r = wn * 32 + nh * 16 + lr;
                    uint32_t bd = bBase + r * 128 + (((c ^ (r & 7))) << 4);
                    uint32_t t0, t1, t2, t3;
                    ldmatrix_x4(t0, t1, t2, t3, bd);
                    b[nh * 2 + 0][0] = t0; b[nh * 2 + 0][1] = t2;
                    b[nh * 2 + 1][0] = t1; b[nh * 2 + 1][1] = t3;
                }
            }
        }

        smem_read = (smem_read + 1 == STAGES) ? 0 : smem_read + 1;
        smem_write = (smem_write + 1 == STAGES) ? 0 : smem_write + 1;
    }

    // --- epilogue: out = acc*half + bias ---
    const int mbase = m0 + wm * 64;
    const int nbase = n0 + wn * 32;
    const int lrow = lane >> 2;
    const int lcol = (lane & 3) * 2;

    #pragma unroll
    for (int nt = 0; nt < 4; nt++) {
        const int col = nbase + nt * 8 + lcol;
        const float bx = __ldg(&bias[col]);
        const float by = __ldg(&bias[col + 1]);
        #pragma unroll
        for (int mt = 0; mt < 4; mt++) {
            const int row0 = mbase + mt * 16 + lrow;
            float2 v0, v1;
            v0.x = acc[mt][nt][0] * halfv + bx;
            v0.y = acc[mt][nt][1] * halfv + by;
            v1.x = acc[mt][nt][2] * halfv + bx;
            v1.y = acc[mt][nt][3] * halfv + by;
            *reinterpret_cast<float2*>(out + (size_t)row0 * NDIM + col) = v0;
            *reinterpret_cast<float2*>(out + (size_t)(row0 + 8) * NDIM + col) = v1;
        }
    }
}

// ---------------------------------------------------------------------------
// Host launch: M-split pipeline across two streams.
//   main: convx(chunk0) ............ wait(evW) GEMM(mt 0..63) . wait(evDone)
//   s2:   reduce1, quantw[+gamma] evW, convx(chunk1), GEMM(mt 64..127) evDone
// The two GEMM halves co-run (shared SM pool, shared L2-resident g_B).
// Streams/events created on the first (uncaptured) call; capture-legal after.
// ---------------------------------------------------------------------------
extern "C" void kernel_launch(void* const* d_in, const int* in_sizes, int n_in,
                              void* d_out, int out_size) {
    // Identify inputs by size: x=67108864, w=16777216, bias=4096
    const float* x = nullptr; const float* w = nullptr; const float* bias = nullptr;
    for (int i = 0; i < n_in; i++) {
        if (in_sizes[i] == MDIM * KDIM)      x = (const float*)d_in[i];
        else if (in_sizes[i] == NDIM * KDIM) w = (const float*)d_in[i];
        else if (in_sizes[i] == NDIM)        bias = (const float*)d_in[i];
    }
    float* out = (float*)d_out;

    const float halfv = (float)((pow(2.0, 1.58) - 1.0) * 0.5);

    static cudaStream_t s2 = nullptr;
    static cudaEvent_t evFork = nullptr, evW = nullptr, evDone = nullptr;
    static bool init_done = false;
    if (!init_done) {
        cudaFuncSetAttribute(k_gemm, cudaFuncAttributeMaxDynamicSharedMemorySize, SMEM_BYTES);
        cudaStreamCreateWithFlags(&s2, cudaStreamNonBlocking);
        cudaEventCreateWithFlags(&evFork, cudaEventDisableTiming);
        cudaEventCreateWithFlags(&evW, cudaEventDisableTiming);
        cudaEventCreateWithFlags(&evDone, cudaEventDisableTiming);
        init_done = true;
    }

    const size_t half4 = (size_t)MDIM * KDIM / 4 / 2;   // float4 elems per M-half
    const int convx_grid = (int)(half4 / 512);          // 16384 blocks
    dim3 gemm_grid(64 * 32);                            // 2048 CTAs per half

    // Fork
    cudaEventRecord(evFork, 0);
    cudaStreamWaitEvent(s2, evFork, 0);

    // s2: w-chain, then chunk-1 conversion, then GEMM half 2
    k_reduce1<<<256, 256, 0, s2>>>(w);
    k_quantw<<<(NDIM * KDIM) / (256 * 4 * 2), 256, 0, s2>>>(w, halfv);
    cudaEventRecord(evW, s2);
    k_convx<<<convx_grid, 256, 0, s2>>>(x, half4);
    k_gemm<<<gemm_grid, 256, SMEM_BYTES, s2>>>(bias, out, halfv, 64);
    cudaEventRecord(evDone, s2);

    // main: chunk-0 conversion, then GEMM half 1 (needs g_B -> wait evW)
    k_convx<<<convx_grid, 256>>>(x, 0);
    cudaStreamWaitEvent(0, evW, 0);
    k_gemm<<<gemm_grid, 256, SMEM_BYTES>>>(bias, out, halfv, 0);

    // Join s2 back into the capture stream
    cudaStreamWaitEvent(0, evDone, 0);
}